// round 15
// baseline (speedup 1.0000x reference)
#include <cuda_runtime.h>
#include <cuda_fp16.h>
#include <math.h>

// Problem dims
#define T_LEN 512
#define M_    4
#define N_    48
#define DIN   52
#define H1_   4160
#define HID_  2320
#define G3_   6960
#define H2_   768
#define DOUT  192

#define NBLK  148
#define NTHR  1024

#define GI_B0   3          // gi/Whh blocks 3..147 (145), 16 units each
#define NGI     145
#define W2_B0   1          // W2 owners: blocks 1..24, 32 rows (2 tiles) each
#define W2_NB   24
#define W1_B0   25         // W1 owners: blocks 25..147 (123), 34 rows each
#define W1_PB   34
#define KT_IH   260        // H1/16
#define KT_HH   145        // HID/16

// ---------------- device scratch ----------------
__device__ __align__(16) uint4 frag_ih[(size_t)NGI * KT_IH * 3 * 32];    // 57.9MB
__device__ __align__(16) uint4 frag_hh[(size_t)NGI * KT_HH * 3 * 32];    // 32.3MB
__device__ __align__(16) uint4 frag_w2[(size_t)W2_NB * KT_HH * 2 * 32];  // 3.6MB
__device__ __align__(16) float w3T[(size_t)H2_ * DOUT];                  // [l2col][row]

__device__ __align__(16) float  g_hf[HID_];
__device__ __align__(16) __half g_hh2[HID_];
__device__ __align__(16) __half g_l1h[H1_ + 64];
__device__ __align__(16) float  g_zpart[W2_NB * DOUT];
__device__ __align__(16) float  g_knet[DIN + 4];
__device__ unsigned g_harr[152];
__device__ unsigned g_rel;
__device__ unsigned g_zfl[24];
__device__ unsigned g_knetfl;

// ---------------- fragment builder ----------------
__device__ __forceinline__ uint4 make_frag(const float* __restrict__ W,
                                           int row0, int k0, int ldk,
                                           int gid, int tig) {
    const float2* p0 = (const float2*)(W + (size_t)(row0 + gid) * ldk + k0 + tig * 2);
    const float2* p1 = (const float2*)(W + (size_t)(row0 + gid + 8) * ldk + k0 + tig * 2);
    float2 f0 = p0[0], f1 = p1[0], f2 = p0[4], f3 = p1[4];
    uint4 r; __half2 h;
    h = __floats2half2_rn(f0.x, f0.y); r.x = *(unsigned*)&h;
    h = __floats2half2_rn(f1.x, f1.y); r.y = *(unsigned*)&h;
    h = __floats2half2_rn(f2.x, f2.y); r.z = *(unsigned*)&h;
    h = __floats2half2_rn(f3.x, f3.y); r.w = *(unsigned*)&h;
    return r;
}

__global__ void cvt_kernel(const float* __restrict__ Wih,
                           const float* __restrict__ Whh,
                           const float* __restrict__ W2,
                           const float* __restrict__ W3) {
    int gw = (blockIdx.x * blockDim.x + threadIdx.x) >> 5;
    int lane = threadIdx.x & 31;
    int nw = (gridDim.x * blockDim.x) >> 5;
    int gid = lane >> 2, tig = lane & 3;

    const int NT_IH = NGI * KT_IH * 3;
    for (int tile = gw; tile < NT_IH; tile += nw) {
        int g = tile % 3; int q = tile / 3;
        int kt = q % KT_IH; int blk = q / KT_IH;
        frag_ih[(size_t)tile * 32 + lane] =
            make_frag(Wih, g * HID_ + blk * 16, kt * 16, H1_, gid, tig);
    }
    const int NT_HH = NGI * KT_HH * 3;
    for (int tile = gw; tile < NT_HH; tile += nw) {
        int g = tile % 3; int q = tile / 3;
        int kt = q % KT_HH; int blk = q / KT_HH;
        frag_hh[(size_t)tile * 32 + lane] =
            make_frag(Whh, g * HID_ + blk * 16, kt * 16, HID_, gid, tig);
    }
    const int NT_W2 = W2_NB * KT_HH * 2;
    for (int tile = gw; tile < NT_W2; tile += nw) {
        int g = tile % 2; int q = tile / 2;
        int kt = q % KT_HH; int w2b = q / KT_HH;
        frag_w2[(size_t)tile * 32 + lane] =
            make_frag(W2, w2b * 32 + g * 16, kt * 16, HID_, gid, tig);
    }
    size_t i0 = (size_t)blockIdx.x * blockDim.x + threadIdx.x;
    size_t st = (size_t)gridDim.x * blockDim.x;
    for (size_t i = i0; i < (size_t)H2_ * DOUT; i += st) {
        size_t c = i / DOUT, r = i % DOUT;
        w3T[i] = W3[r * H2_ + c];
    }
}

// ---------------- store-based grid barrier ----------------
__device__ __forceinline__ void grid_barrier2(int bid, unsigned tag) {
    __syncthreads();
    if (threadIdx.x == 0) {
        __threadfence();
        *((volatile unsigned*)&g_harr[bid]) = tag;
    }
    if (bid == 0 && threadIdx.x < 32) {
        int lane = threadIdx.x;
        for (;;) {
            unsigned v0 = 0xffffffffu, v1 = 0xffffffffu, v2 = 0xffffffffu;
            unsigned v3 = 0xffffffffu, v4 = 0xffffffffu;
            { int i = lane;       if (i < NBLK) v0 = *((volatile unsigned*)&g_harr[i]); }
            { int i = lane + 32;  if (i < NBLK) v1 = *((volatile unsigned*)&g_harr[i]); }
            { int i = lane + 64;  if (i < NBLK) v2 = *((volatile unsigned*)&g_harr[i]); }
            { int i = lane + 96;  if (i < NBLK) v3 = *((volatile unsigned*)&g_harr[i]); }
            { int i = lane + 128; if (i < NBLK) v4 = *((volatile unsigned*)&g_harr[i]); }
            unsigned mn = min(min(min(v0, v1), min(v2, v3)), v4);
#pragma unroll
            for (int o = 16; o; o >>= 1) {
                unsigned v = __shfl_down_sync(0xffffffffu, mn, o);
                if (v < mn) mn = v;
            }
            mn = __shfl_sync(0xffffffffu, mn, 0);
            if (mn >= tag) break;
        }
        if (lane == 0) { __threadfence(); *((volatile unsigned*)&g_rel) = tag; }
    }
    if (threadIdx.x == 0) {
        while (*((volatile unsigned*)&g_rel) < tag) { }
        __threadfence();
    }
    __syncthreads();
}

// ---------------- mma ----------------
__device__ __forceinline__ void mma16816(float* c, uint4 a, unsigned b0, unsigned b1) {
    asm volatile(
        "mma.sync.aligned.m16n8k16.row.col.f32.f16.f16.f32 "
        "{%0,%1,%2,%3},{%4,%5,%6,%7},{%8,%9},{%0,%1,%2,%3};"
        : "+f"(c[0]), "+f"(c[1]), "+f"(c[2]), "+f"(c[3])
        : "r"(a.x), "r"(a.y), "r"(a.z), "r"(a.w), "r"(b0), "r"(b1));
}

// Warp-per-gate pass: NG gate-tiles, WPG warps per gate, depth-4 ring.
// frag layout: fb[(kt*NG + gate)*32 + lane]. partials -> s_red[wid*16 + row]
template <int NT, int NG, int WPG>
__device__ __forceinline__ void mma_gate_pass(const uint4* __restrict__ fb,
                                              const unsigned* __restrict__ vech2,
                                              float* __restrict__ s_red,
                                              int wid, int lane) {
    if (wid >= NG * WPG) return;
    const int gate = wid / WPG, kidx = wid % WPG;
    const int gid = lane >> 2, tig = lane & 3;
    float c[4] = {0.f, 0.f, 0.f, 0.f};
    uint4 ring[4];
    const int nk = (NT - kidx + WPG - 1) / WPG;
#pragma unroll
    for (int s = 0; s < 4; ++s) {
        int kt = kidx + s * WPG;
        if (s < nk) ring[s] = fb[(size_t)(kt * NG + gate) * 32 + lane];
    }
    for (int i0 = 0; i0 < nk; i0 += 4) {
#pragma unroll
        for (int s = 0; s < 4; ++s) {
            int i = i0 + s;
            if (i < nk) {
                int kt = kidx + i * WPG;
                uint4 a = ring[s];
                int kp = i + 4;
                if (kp < nk) ring[s] = fb[(size_t)((kidx + kp * WPG) * NG + gate) * 32 + lane];
                unsigned b0 = 0, b1 = 0;
                if (gid == 0) { b0 = vech2[kt * 8 + tig]; b1 = vech2[kt * 8 + 4 + tig]; }
                mma16816(c, a, b0, b1);
            }
        }
    }
    if (tig == 0) {
        s_red[wid * 16 + gid]     = c[0];
        s_red[wid * 16 + gid + 8] = c[2];
    }
}

__device__ __forceinline__ float sigmoidf_(float x) {
    return 1.f / (1.f + __expf(-x));
}

// ---------------- persistent kernel ----------------
__global__ void __launch_bounds__(NTHR, 1)
kalmannet_kernel(const float* __restrict__ A,   const float* __restrict__ C,
                 const float* __restrict__ x0,  const float* __restrict__ h0,
                 const float* __restrict__ y,   const float* __restrict__ W1,
                 const float* __restrict__ b1,  const float* __restrict__ bih,
                 const float* __restrict__ bhh, const float* __restrict__ b2,
                 const float* __restrict__ b3,  float* __restrict__ out) {
    const int tid  = threadIdx.x;
    const int bid  = blockIdx.x;
    const int wid  = tid >> 5;
    const int lane = tid & 31;

    const bool isGI = (bid >= GI_B0);
    const bool isW2 = (bid >= W2_B0 && bid < W2_B0 + W2_NB);
    const bool isW1 = (bid >= W1_B0);
    const int  ub   = isGI ? (bid - GI_B0) * 16 : 0;

    __shared__ __align__(16) uint4 s_x[H1_ / 8];       // h(half2) then l1(half2)
    __shared__ __align__(16) float s_red[32 * 16];
    __shared__ __align__(16) float s_ghv[48];
    __shared__ __align__(16) float s_giv[48];
    __shared__ __align__(16) float s_l2c[32];
    __shared__ __align__(16) float s_z[DOUT];
    __shared__ __align__(16) float s_knet[56];
    __shared__ float s_dy[N_];
    __shared__ float s_xprior[M_], s_xpost[M_], s_xprev[M_];

    const unsigned* vech2 = (const unsigned*)s_x;

    for (int t = 0; t < T_LEN; ++t) {
        // ---- stage h(t-1) as half2 (blocks 1..147) ----
        if (bid != 0) {
            if (t == 0) {
                for (int i = tid; i < HID_ / 2; i += NTHR) {
                    float2 f = ((const float2*)h0)[i];
                    ((__half2*)s_x)[i] = __floats2half2_rn(f.x, f.y);
                }
            } else {
                const uint4* src = (const uint4*)g_hh2;
                for (int i = tid; i < HID_ / 8; i += NTHR) s_x[i] = src[i];
            }
            __syncthreads();
        }

        // ---- W2 owners: 32-row MMA + W3 partial (t>0) ----
        if (isW2 && t > 0) {
            mma_gate_pass<KT_HH, 2, 16>(frag_w2 + (size_t)(bid - W2_B0) * KT_HH * 2 * 32,
                                        vech2, s_red, wid, lane);
            __syncthreads();
            if (tid < 32) {
                int g = tid >> 4, r = tid & 15;
                float s = 0.f;
#pragma unroll
                for (int k = 0; k < 16; ++k) s += s_red[(g * 16 + k) * 16 + r];
                s_l2c[tid] = fmaxf(s + b2[(bid - W2_B0) * 32 + tid], 0.f);
            }
            __syncthreads();
            if (tid < DOUT) {
                int c0 = (bid - W2_B0) * 32;
                float acc = 0.f;
#pragma unroll
                for (int i = 0; i < 32; ++i)
                    acc = fmaf(w3T[(size_t)(c0 + i) * DOUT + tid], s_l2c[i], acc);
                g_zpart[(bid - W2_B0) * DOUT + tid] = acc;
            }
            __threadfence();
            __syncthreads();
            if (tid == 0) *((volatile unsigned*)&g_zfl[bid - W2_B0]) = (unsigned)t;
            __syncthreads();
        }

        // ---- Whh MMA (gi blocks) ----
        if (isGI) {
            mma_gate_pass<KT_HH, 3, 10>(frag_hh + (size_t)(bid - GI_B0) * KT_HH * 3 * 32,
                                        vech2, s_red, wid, lane);
            __syncthreads();
            if (tid < 48) {
                int g = tid >> 4, r = tid & 15;
                float s = 0.f;
#pragma unroll
                for (int k = 0; k < 10; ++k) s += s_red[(g * 10 + k) * 16 + r];
                s_ghv[tid] = s;
            }
            __syncthreads();
        }

        // ---- block 0: serial chain -> knet ----
        if (bid == 0) {
            if (t > 0) {
                if (wid == 0) {
                    for (;;) {
                        unsigned v = (lane < W2_NB) ? *((volatile unsigned*)&g_zfl[lane]) : 0xffffffffu;
                        unsigned mn = v;
#pragma unroll
                        for (int o = 16; o; o >>= 1) {
                            unsigned w = __shfl_down_sync(0xffffffffu, mn, o);
                            if (w < mn) mn = w;
                        }
                        mn = __shfl_sync(0xffffffffu, mn, 0);
                        if (mn >= (unsigned)t) break;
                    }
                    if (lane == 0) __threadfence();
                }
                __syncthreads();
                for (int j = tid; j < DOUT; j += NTHR) {
                    float acc = b3[j];
#pragma unroll 8
                    for (int c = 0; c < W2_NB; ++c) acc += g_zpart[c * DOUT + j];
                    s_z[j] = acc * 1e-4f;
                }
                __syncthreads();
            }
            if (wid == 0) {
                if (t == 0) {
                    if (lane < M_) { s_xpost[lane] = x0[lane]; s_xprev[lane] = x0[lane]; }
                    __syncwarp();
                } else {
                    if (lane < M_) {
                        float acc = 0.f;
#pragma unroll 4
                        for (int j = 0; j < N_; ++j)
                            acc = fmaf(s_z[lane * N_ + j], s_dy[j], acc);
                        float xp = s_xprior[lane] + acc;
                        s_xprev[lane] = s_xprior[lane];
                        s_xpost[lane] = xp;
                        out[lane * T_LEN + (t - 1)] = xp;
                    }
                    __syncwarp();
                }
                if (lane < M_) {
                    float acc = 0.f;
#pragma unroll
                    for (int k = 0; k < M_; ++k) acc = fmaf(A[lane * M_ + k], s_xpost[k], acc);
                    s_xprior[lane] = acc;
                }
                __syncwarp();
                for (int j = lane; j < N_; j += 32) {
                    float m = C[j * (M_ + 1) + M_];
#pragma unroll
                    for (int k = 0; k < M_; ++k) m = fmaf(C[j * (M_ + 1) + k], s_xprior[k], m);
                    s_dy[j] = y[j * T_LEN + t] - m;
                }
                __syncwarp();
                float sq = 0.f;
                for (int j = lane; j < N_; j += 32) sq += s_dy[j] * s_dy[j];
#pragma unroll
                for (int o = 16; o; o >>= 1) sq += __shfl_down_sync(0xffffffffu, sq, o);
                sq = __shfl_sync(0xffffffffu, sq, 0);
                float inv = 1.f / fmaxf(sqrtf(sq), 1e-12f);
                for (int j = lane; j < N_; j += 32) g_knet[j] = s_dy[j] * inv;

                float dx = (lane < M_) ? (s_xpost[lane] - s_xprev[lane]) : 0.f;
                float sq2 = dx * dx;
#pragma unroll
                for (int o = 16; o; o >>= 1) sq2 += __shfl_down_sync(0xffffffffu, sq2, o);
                sq2 = __shfl_sync(0xffffffffu, sq2, 0);
                float inv2 = 1.f / fmaxf(sqrtf(sq2), 1e-12f);
                if (lane < M_) g_knet[N_ + lane] = dx * inv2;
                __syncwarp();
                if (lane == 0) {
                    __threadfence();
                    *((volatile unsigned*)&g_knetfl) = (unsigned)(t + 1);
                }
            }
        }

        // ---- W1: blocks 25..147, 34 rows each ----
        if (isW1) {
            if (tid == 0) {
                while (*((volatile unsigned*)&g_knetfl) < (unsigned)(t + 1)) { }
                __threadfence();
            }
            __syncthreads();
            if (tid < 56) s_knet[tid] = g_knet[tid];
            __syncthreads();
            if (tid < W1_PB) {
                int r = (bid - W1_B0) * W1_PB + tid;
                if (r < H1_) {
                    const float4* w4 = (const float4*)(W1 + (size_t)r * DIN);
                    const float4* k4 = (const float4*)s_knet;
                    float acc = b1[r];
#pragma unroll
                    for (int c = 0; c < DIN / 4; ++c) {
                        float4 a = w4[c], b = k4[c];
                        acc = fmaf(a.x, b.x, acc); acc = fmaf(a.y, b.y, acc);
                        acc = fmaf(a.z, b.z, acc); acc = fmaf(a.w, b.w, acc);
                    }
                    g_l1h[r] = __float2half(fmaxf(acc, 0.f));
                }
            }
        }

        grid_barrier2(bid, 2u * (unsigned)t + 1u);

        // ---- gi MMA + gate ----
        if (isGI) {
            const uint4* src = (const uint4*)g_l1h;
            for (int i = tid; i < H1_ / 8; i += NTHR) s_x[i] = src[i];
            __syncthreads();
            mma_gate_pass<KT_IH, 3, 10>(frag_ih + (size_t)(bid - GI_B0) * KT_IH * 3 * 32,
                                        vech2, s_red, wid, lane);
            __syncthreads();
            if (tid < 48) {
                int g = tid >> 4, r = tid & 15;
                float s = 0.f;
#pragma unroll
                for (int k = 0; k < 10; ++k) s += s_red[(g * 10 + k) * 16 + r];
                s_giv[tid] = s;
            }
            __syncthreads();
            if (tid < 16) {
                int u = ub + tid;
                float gir = s_giv[tid]      + bih[u];
                float giz = s_giv[16 + tid] + bih[u + HID_];
                float gin = s_giv[32 + tid] + bih[u + 2 * HID_];
                float ghr = s_ghv[tid]      + bhh[u];
                float ghz = s_ghv[16 + tid] + bhh[u + HID_];
                float ghn = s_ghv[32 + tid] + bhh[u + 2 * HID_];
                float hold = (t == 0) ? h0[u] : g_hf[u];
                float rg = sigmoidf_(gir + ghr);
                float zg = sigmoidf_(giz + ghz);
                float ng = tanhf(gin + rg * ghn);
                float hv = (1.f - zg) * ng + zg * hold;
                g_hf[u]  = hv;
                g_hh2[u] = __float2half(hv);
            }
        }
        grid_barrier2(bid, 2u * (unsigned)t + 2u);
    }

    // ================= epilogue: x_post(T-1) =================
    if (isW2) {
        const uint4* src = (const uint4*)g_hh2;
        for (int i = tid; i < HID_ / 8; i += NTHR) s_x[i] = src[i];
        __syncthreads();
        mma_gate_pass<KT_HH, 2, 16>(frag_w2 + (size_t)(bid - W2_B0) * KT_HH * 2 * 32,
                                    vech2, s_red, wid, lane);
        __syncthreads();
        if (tid < 32) {
            int g = tid >> 4, r = tid & 15;
            float s = 0.f;
#pragma unroll
            for (int k = 0; k < 16; ++k) s += s_red[(g * 16 + k) * 16 + r];
            s_l2c[tid] = fmaxf(s + b2[(bid - W2_B0) * 32 + tid], 0.f);
        }
        __syncthreads();
        if (tid < DOUT) {
            int c0 = (bid - W2_B0) * 32;
            float acc = 0.f;
#pragma unroll
            for (int i = 0; i < 32; ++i)
                acc = fmaf(w3T[(size_t)(c0 + i) * DOUT + tid], s_l2c[i], acc);
            g_zpart[(bid - W2_B0) * DOUT + tid] = acc;
        }
        __threadfence();
        __syncthreads();
        if (tid == 0) *((volatile unsigned*)&g_zfl[bid - W2_B0]) = (unsigned)T_LEN;
    }
    if (bid == 0) {
        if (wid == 0) {
            for (;;) {
                unsigned v = (lane < W2_NB) ? *((volatile unsigned*)&g_zfl[lane]) : 0xffffffffu;
                unsigned mn = v;
#pragma unroll
                for (int o = 16; o; o >>= 1) {
                    unsigned w = __shfl_down_sync(0xffffffffu, mn, o);
                    if (w < mn) mn = w;
                }
                mn = __shfl_sync(0xffffffffu, mn, 0);
                if (mn >= (unsigned)T_LEN) break;
            }
            if (lane == 0) __threadfence();
        }
        __syncthreads();
        for (int j = tid; j < DOUT; j += NTHR) {
            float acc = b3[j];
#pragma unroll 8
            for (int c = 0; c < W2_NB; ++c) acc += g_zpart[c * DOUT + j];
            s_z[j] = acc * 1e-4f;
        }
        __syncthreads();
        if (tid < M_) {
            float acc = 0.f;
#pragma unroll 4
            for (int j = 0; j < N_; ++j) acc = fmaf(s_z[tid * N_ + j], s_dy[j], acc);
            out[tid * T_LEN + (T_LEN - 1)] = s_xprior[tid] + acc;
        }
        __syncthreads();
        // reset all sync state for graph replay
        if (tid < W2_NB) *((volatile unsigned*)&g_zfl[tid]) = 0u;
        if (tid < NBLK)  *((volatile unsigned*)&g_harr[tid]) = 0u;
        if (tid == 0) {
            *((volatile unsigned*)&g_knetfl) = 0u;
            *((volatile unsigned*)&g_rel)    = 0u;
            __threadfence();
        }
    }
}

// ---------------- launch ----------------
extern "C" void kernel_launch(void* const* d_in, const int* in_sizes, int n_in,
                              void* d_out, int out_size) {
    const float* A    = (const float*)d_in[0];
    const float* C    = (const float*)d_in[1];
    const float* x0   = (const float*)d_in[2];
    const float* h0   = (const float*)d_in[3];
    const float* y    = (const float*)d_in[4];
    const float* W1   = (const float*)d_in[5];
    const float* b1   = (const float*)d_in[6];
    const float* Wih  = (const float*)d_in[7];
    const float* Whh  = (const float*)d_in[8];
    const float* bih  = (const float*)d_in[9];
    const float* bhh  = (const float*)d_in[10];
    const float* W2   = (const float*)d_in[11];
    const float* b2   = (const float*)d_in[12];
    const float* W3   = (const float*)d_in[13];
    const float* b3   = (const float*)d_in[14];
    float* out = (float*)d_out;

    cvt_kernel<<<2048, 256>>>(Wih, Whh, W2, W3);
    kalmannet_kernel<<<NBLK, NTHR>>>(A, C, x0, h0, y, W1, b1, bih, bhh,
                                     b2, b3, out);
}

// round 16
// speedup vs baseline: 1.3408x; 1.3408x over previous
#include <cuda_runtime.h>
#include <cuda_fp16.h>
#include <math.h>

// Problem dims
#define T_LEN 512
#define M_    4
#define N_    48
#define DIN   52
#define H1_   4160
#define HID_  2320
#define G3_   6960
#define H2_   768
#define DOUT  192

#define NBLK  148
#define NTHR  1024
#define NWARP 32

// roles (identical to R10)
#define FR_LO   1
#define FR_HI   32
#define FR_NB   32
#define L2CH    24        // l2 rows per front block (32*24 = 768)
#define W1_PB   130       // W1 rows per front block (32*130 = 4160)
#define WHM_LO  33        // Whh main blocks 33..147 (115)
#define WHM_U   16        // units each (115*16 = 1840)
#define WHF_U   15        // front blocks: 15 units each (32*15 = 480)
#define WHF_BASE 1840

// ---------------- device scratch ----------------
__device__ __align__(16) __half w_ihH[(size_t)G3_ * H1_];
__device__ __align__(16) __half w_hhH[(size_t)G3_ * HID_];
__device__ __align__(16) __half w2H[(size_t)H2_ * HID_];
__device__ __align__(16) float  w3T[(size_t)H2_ * DOUT];   // [col][row] fp32

__device__ __align__(16) float  g_hf[HID_];
__device__ __align__(16) __half g_hh2[HID_];
__device__ __align__(16) __half g_l1h[H1_];
__device__ __align__(16) float  g_gh[G3_];
__device__ __align__(16) float  g_zpart[FR_NB * DOUT];
__device__ __align__(16) float  g_knet[DIN + 4];
__device__ unsigned g_zdone, g_knetflag, g_l1done;
__device__ unsigned g_harr[152];
__device__ unsigned g_rel;

// ---------------- conversion kernel ----------------
__device__ __forceinline__ void cvt8(const float* __restrict__ src,
                                     __half* __restrict__ dst, size_t g) {
    const float4* s4 = (const float4*)src;
    float4 a = s4[2 * g], b = s4[2 * g + 1];
    __half2 h0 = __floats2half2_rn(a.x, a.y);
    __half2 h1 = __floats2half2_rn(a.z, a.w);
    __half2 h2 = __floats2half2_rn(b.x, b.y);
    __half2 h3 = __floats2half2_rn(b.z, b.w);
    uint4 o;
    o.x = *(unsigned*)&h0; o.y = *(unsigned*)&h1;
    o.z = *(unsigned*)&h2; o.w = *(unsigned*)&h3;
    ((uint4*)dst)[g] = o;
}

__global__ void cvt_kernel(const float* __restrict__ Wih,
                           const float* __restrict__ Whh,
                           const float* __restrict__ W2,
                           const float* __restrict__ W3) {
    size_t i0 = (size_t)blockIdx.x * blockDim.x + threadIdx.x;
    size_t st = (size_t)gridDim.x * blockDim.x;
    const size_t nIH = (size_t)G3_ * H1_ / 8, nHH = (size_t)G3_ * HID_ / 8;
    const size_t n2 = (size_t)H2_ * HID_ / 8;
    const size_t n3 = (size_t)H2_ * DOUT;
    for (size_t g = i0; g < nIH; g += st) cvt8(Wih, w_ihH, g);
    for (size_t g = i0; g < nHH; g += st) cvt8(Whh, w_hhH, g);
    for (size_t g = i0; g < n2;  g += st) cvt8(W2, w2H, g);
    for (size_t i = i0; i < n3; i += st) {
        size_t c = i / DOUT, r = i % DOUT;
        w3T[i] = W3[r * H2_ + c];
    }
}

// ---------------- sync primitives ----------------
// store-based grid barrier (validated R14/R15)
__device__ __forceinline__ void grid_barrier2(int bid, unsigned tag) {
    __syncthreads();
    if (threadIdx.x == 0) {
        __threadfence();
        *((volatile unsigned*)&g_harr[bid]) = tag;
    }
    if (bid == 0 && threadIdx.x < 32) {
        int lane = threadIdx.x;
        for (;;) {
            unsigned v0 = 0xffffffffu, v1 = 0xffffffffu, v2 = 0xffffffffu;
            unsigned v3 = 0xffffffffu, v4 = 0xffffffffu;
            { int i = lane;       if (i < NBLK) v0 = *((volatile unsigned*)&g_harr[i]); }
            { int i = lane + 32;  if (i < NBLK) v1 = *((volatile unsigned*)&g_harr[i]); }
            { int i = lane + 64;  if (i < NBLK) v2 = *((volatile unsigned*)&g_harr[i]); }
            { int i = lane + 96;  if (i < NBLK) v3 = *((volatile unsigned*)&g_harr[i]); }
            { int i = lane + 128; if (i < NBLK) v4 = *((volatile unsigned*)&g_harr[i]); }
            unsigned mn = min(min(min(v0, v1), min(v2, v3)), v4);
#pragma unroll
            for (int o = 16; o; o >>= 1) {
                unsigned v = __shfl_down_sync(0xffffffffu, mn, o);
                if (v < mn) mn = v;
            }
            mn = __shfl_sync(0xffffffffu, mn, 0);
            if (mn >= tag) break;
        }
        if (lane == 0) { __threadfence(); *((volatile unsigned*)&g_rel) = tag; }
    }
    if (threadIdx.x == 0) {
        while (*((volatile unsigned*)&g_rel) < tag) { }
        __threadfence();
    }
    __syncthreads();
}

__device__ __forceinline__ void signal_done(unsigned* ctr) {
    __syncthreads();
    if (threadIdx.x == 0) { __threadfence(); atomicAdd(ctr, 1u); }
}
__device__ __forceinline__ void wait_ctr(unsigned* ctr, unsigned target) {
    if (threadIdx.x == 0) {
        while (*((volatile unsigned*)ctr) < target) { }
        __threadfence();
    }
    __syncthreads();
}

#define H2AT(u) (*(const __half2*)&(u))

// ---------------- dots (R10 verbatim) ----------------
template <int N8>
__device__ __forceinline__ float3 dot3_half(const __half* __restrict__ wa,
                                            const __half* __restrict__ wb,
                                            const __half* __restrict__ wc,
                                            const uint4* __restrict__ xs) {
    constexpr int KF  = N8 / 32;
    constexpr int REM = N8 % 32;
    const uint4* A  = (const uint4*)wa;
    const uint4* B  = (const uint4*)wb;
    const uint4* Cc = (const uint4*)wc;
    const int lane = threadIdx.x & 31;
    uint4 rA[2], rB[2], rC[2];
#pragma unroll
    for (int s = 0; s < 2; ++s)
        if (s < KF) { int c = s * 32 + lane; rA[s] = A[c]; rB[s] = B[c]; rC[s] = Cc[c]; }
    __half2 z = __float2half2_rn(0.f);
    __half2 a0 = z, a1 = z, b0 = z, b1 = z, c0 = z, c1 = z;
#pragma unroll
    for (int k = 0; k < KF; ++k) {
        const int sl = k & 1;
        uint4 u = rA[sl], v = rB[sl], w = rC[sl];
        if (k + 2 < KF) { int c = (k + 2) * 32 + lane; rA[sl] = A[c]; rB[sl] = B[c]; rC[sl] = Cc[c]; }
        uint4 xv = xs[k * 32 + lane];
        a0 = __hfma2(H2AT(u.x), H2AT(xv.x), a0);
        a1 = __hfma2(H2AT(u.y), H2AT(xv.y), a1);
        a0 = __hfma2(H2AT(u.z), H2AT(xv.z), a0);
        a1 = __hfma2(H2AT(u.w), H2AT(xv.w), a1);
        b0 = __hfma2(H2AT(v.x), H2AT(xv.x), b0);
        b1 = __hfma2(H2AT(v.y), H2AT(xv.y), b1);
        b0 = __hfma2(H2AT(v.z), H2AT(xv.z), b0);
        b1 = __hfma2(H2AT(v.w), H2AT(xv.w), b1);
        c0 = __hfma2(H2AT(w.x), H2AT(xv.x), c0);
        c1 = __hfma2(H2AT(w.y), H2AT(xv.y), c1);
        c0 = __hfma2(H2AT(w.z), H2AT(xv.z), c0);
        c1 = __hfma2(H2AT(w.w), H2AT(xv.w), c1);
    }
    if (REM > 0 && lane < REM) {
        int c = KF * 32 + lane;
        uint4 u = A[c], v = B[c], w = Cc[c], xv = xs[c];
        a0 = __hfma2(H2AT(u.x), H2AT(xv.x), a0);
        a1 = __hfma2(H2AT(u.y), H2AT(xv.y), a1);
        a0 = __hfma2(H2AT(u.z), H2AT(xv.z), a0);
        a1 = __hfma2(H2AT(u.w), H2AT(xv.w), a1);
        b0 = __hfma2(H2AT(v.x), H2AT(xv.x), b0);
        b1 = __hfma2(H2AT(v.y), H2AT(xv.y), b1);
        b0 = __hfma2(H2AT(v.z), H2AT(xv.z), b0);
        b1 = __hfma2(H2AT(v.w), H2AT(xv.w), b1);
        c0 = __hfma2(H2AT(w.x), H2AT(xv.x), c0);
        c1 = __hfma2(H2AT(w.y), H2AT(xv.y), c1);
        c0 = __hfma2(H2AT(w.z), H2AT(xv.z), c0);
        c1 = __hfma2(H2AT(w.w), H2AT(xv.w), c1);
    }
    float2 fa0 = __half22float2(a0), fa1 = __half22float2(a1);
    float2 fb0 = __half22float2(b0), fb1 = __half22float2(b1);
    float2 fc0 = __half22float2(c0), fc1 = __half22float2(c1);
    float ra = (fa0.x + fa0.y) + (fa1.x + fa1.y);
    float rb = (fb0.x + fb0.y) + (fb1.x + fb1.y);
    float rc = (fc0.x + fc0.y) + (fc1.x + fc1.y);
#pragma unroll
    for (int o = 16; o; o >>= 1) {
        ra += __shfl_down_sync(0xffffffffu, ra, o);
        rb += __shfl_down_sync(0xffffffffu, rb, o);
        rc += __shfl_down_sync(0xffffffffu, rc, o);
    }
    return make_float3(ra, rb, rc);
}

template <int N8>
__device__ __forceinline__ float dot_row(const __half* __restrict__ w,
                                         const uint4* __restrict__ xs) {
    constexpr int KF  = N8 / 32;
    constexpr int REM = N8 % 32;
    const uint4* W = (const uint4*)w;
    const int lane = threadIdx.x & 31;
    uint4 rW[4];
#pragma unroll
    for (int s = 0; s < 4; ++s)
        if (s < KF) rW[s] = W[s * 32 + lane];
    __half2 z = __float2half2_rn(0.f);
    __half2 a0 = z, a1 = z, a2 = z, a3 = z;
#pragma unroll
    for (int k = 0; k < KF; ++k) {
        const int sl = k & 3;
        uint4 wv = rW[sl];
        if (k + 4 < KF) rW[sl] = W[(k + 4) * 32 + lane];
        uint4 xv = xs[k * 32 + lane];
        a0 = __hfma2(H2AT(wv.x), H2AT(xv.x), a0);
        a1 = __hfma2(H2AT(wv.y), H2AT(xv.y), a1);
        a2 = __hfma2(H2AT(wv.z), H2AT(xv.z), a2);
        a3 = __hfma2(H2AT(wv.w), H2AT(xv.w), a3);
    }
    if (REM > 0 && lane < REM) {
        int c = KF * 32 + lane;
        uint4 wv = W[c], xv = xs[c];
        a0 = __hfma2(H2AT(wv.x), H2AT(xv.x), a0);
        a1 = __hfma2(H2AT(wv.y), H2AT(xv.y), a1);
        a2 = __hfma2(H2AT(wv.z), H2AT(xv.z), a2);
        a3 = __hfma2(H2AT(wv.w), H2AT(xv.w), a3);
    }
    float2 f0 = __half22float2(a0), f1 = __half22float2(a1);
    float2 f2 = __half22float2(a2), f3 = __half22float2(a3);
    float acc = ((f0.x + f0.y) + (f1.x + f1.y)) + ((f2.x + f2.y) + (f3.x + f3.y));
#pragma unroll
    for (int o = 16; o; o >>= 1) acc += __shfl_down_sync(0xffffffffu, acc, o);
    return acc;
}

__device__ __forceinline__ float sigmoidf_(float x) {
    return 1.f / (1.f + __expf(-x));
}

// ---------------- persistent kernel ----------------
__global__ void __launch_bounds__(NTHR, 1)
kalmannet_kernel(const float* __restrict__ A,   const float* __restrict__ C,
                 const float* __restrict__ x0,  const float* __restrict__ h0,
                 const float* __restrict__ y,   const float* __restrict__ W1,
                 const float* __restrict__ b1,  const float* __restrict__ bih,
                 const float* __restrict__ bhh, const float* __restrict__ b2,
                 const float* __restrict__ b3,  float* __restrict__ out) {
    const int tid  = threadIdx.x;
    const int bid  = blockIdx.x;
    const int wid  = tid >> 5;
    const int lane = tid & 31;

    __shared__ __align__(16) uint4 s_x[H1_ / 8];      // h (half2) then l1 (half2)
    __shared__ __align__(16) float s_part[NWARP][4];
    __shared__ __align__(16) float s_l2c[L2CH];
    __shared__ __align__(16) float s_z[DOUT];
    __shared__ __align__(16) float s_knet[56];
    __shared__ float s_dy[N_];
    __shared__ float s_xprior[M_], s_xpost[M_], s_xprev[M_];

    const bool isF = (bid >= FR_LO && bid <= FR_HI);

    for (int t = 0; t < T_LEN; ++t) {
        if (bid != 0) {
            // ---------- stage h(t-1) ----------
            if (t == 0) {
                for (int i = tid; i < HID_ / 2; i += NTHR) {
                    float2 f = ((const float2*)h0)[i];
                    ((__half2*)s_x)[i] = __floats2half2_rn(f.x, f.y);
                }
            } else {
                const uint4* src = (const uint4*)g_hh2;
                for (int i = tid; i < HID_ / 8; i += NTHR) s_x[i] = src[i];
            }
            __syncthreads();

            if (isF) {
                // ---------- W2 chunk + W3 partial (t>0) ----------
                if (t > 0) {
                    if (wid < L2CH) {
                        int r = (bid - 1) * L2CH + wid;
                        float v = dot_row<HID_ / 8>(w2H + (size_t)r * HID_, s_x);
                        if (lane == 0) s_l2c[wid] = fmaxf(v + b2[r], 0.f);
                    }
                    __syncthreads();
                    if (tid < DOUT) {
                        int c0 = (bid - 1) * L2CH;
                        float acc = 0.f;
#pragma unroll
                        for (int j = 0; j < L2CH; ++j)
                            acc = fmaf(w3T[(size_t)(c0 + j) * DOUT + tid], s_l2c[j], acc);
                        g_zpart[(bid - 1) * DOUT + tid] = acc;
                    }
                    signal_done(&g_zdone);
                }
                // ---------- W1: wait knet, 130 rows ----------
                if (tid == 0) {
                    while (*((volatile unsigned*)&g_knetflag) < (unsigned)(t + 1)) { }
                    __threadfence();
                }
                __syncthreads();
                if (tid < 56) s_knet[tid] = g_knet[tid];
                __syncthreads();
                if (wid <= 16) {
                    int ri = wid * 8 + (lane >> 2);          // 0..135
                    int part = lane & 3;
                    int ric = (ri < W1_PB) ? ri : (W1_PB - 1);
                    int rowg = (bid - 1) * W1_PB + ric;
                    const float4* w4 = (const float4*)(W1 + (size_t)rowg * DIN);
                    const float4* k4 = (const float4*)s_knet;
                    float acc = 0.f;
                    float4 aa, bb;
                    aa = w4[part];     bb = k4[part];
                    acc = fmaf(aa.x, bb.x, acc); acc = fmaf(aa.y, bb.y, acc);
                    acc = fmaf(aa.z, bb.z, acc); acc = fmaf(aa.w, bb.w, acc);
                    aa = w4[part + 4]; bb = k4[part + 4];
                    acc = fmaf(aa.x, bb.x, acc); acc = fmaf(aa.y, bb.y, acc);
                    acc = fmaf(aa.z, bb.z, acc); acc = fmaf(aa.w, bb.w, acc);
                    aa = w4[part + 8]; bb = k4[part + 8];
                    acc = fmaf(aa.x, bb.x, acc); acc = fmaf(aa.y, bb.y, acc);
                    acc = fmaf(aa.z, bb.z, acc); acc = fmaf(aa.w, bb.w, acc);
                    if (part == 0) {
                        aa = w4[12]; bb = k4[12];
                        acc = fmaf(aa.x, bb.x, acc); acc = fmaf(aa.y, bb.y, acc);
                        acc = fmaf(aa.z, bb.z, acc); acc = fmaf(aa.w, bb.w, acc);
                        acc += b1[rowg];
                    }
                    acc += __shfl_down_sync(0xffffffffu, acc, 2);
                    acc += __shfl_down_sync(0xffffffffu, acc, 1);
                    if (part == 0 && ri < W1_PB)
                        g_l1h[rowg] = __float2half(fmaxf(acc, 0.f));
                }
                signal_done(&g_l1done);
            }

            // ---------- Whh units ----------
            {
                int uu = wid & 15, half = wid >> 4;
                int nu = isF ? WHF_U : WHM_U;
                if (uu < nu) {
                    int u = isF ? (WHF_BASE + (bid - FR_LO) * WHF_U + uu)
                                : ((bid - WHM_LO) * WHM_U + uu);
                    const __half* wa = w_hhH + (size_t)u * HID_ + half * 1160;
                    const __half* wb = w_hhH + (size_t)(u + HID_) * HID_ + half * 1160;
                    const __half* wc = w_hhH + (size_t)(u + 2 * HID_) * HID_ + half * 1160;
                    float3 g = dot3_half<145>(wa, wb, wc, s_x + half * 145);
                    if (lane == 0) {
                        s_part[wid][0] = g.x;
                        s_part[wid][1] = g.y;
                        s_part[wid][2] = g.z;
                    }
                }
                __syncthreads();
                if (tid < (isF ? WHF_U : WHM_U)) {
                    int u = isF ? (WHF_BASE + (bid - FR_LO) * WHF_U + tid)
                                : ((bid - WHM_LO) * WHM_U + tid);
                    g_gh[u]            = s_part[tid][0] + s_part[tid + 16][0] + bhh[u];
                    g_gh[u + HID_]     = s_part[tid][1] + s_part[tid + 16][1] + bhh[u + HID_];
                    g_gh[u + 2 * HID_] = s_part[tid][2] + s_part[tid + 16][2] + bhh[u + 2 * HID_];
                }
                __syncthreads();
            }
        } else {
            // ---------- block 0: chain ----------
            if (t == 0) {
                if (tid < M_) { s_xpost[tid] = x0[tid]; s_xprev[tid] = x0[tid]; }
                __syncthreads();
            } else {
                wait_ctr(&g_zdone, (unsigned)FR_NB * (unsigned)t);
                if (tid < DOUT) {
                    float acc = b3[tid];
#pragma unroll
                    for (int c = 0; c < FR_NB; ++c) acc += g_zpart[c * DOUT + tid];
                    s_z[tid] = acc * 1e-4f;
                }
                __syncthreads();
                if (tid < M_) {
                    float acc = 0.f;
#pragma unroll 4
                    for (int j = 0; j < N_; ++j)
                        acc = fmaf(s_z[tid * N_ + j], s_dy[j], acc);
                    float xp = s_xprior[tid] + acc;
                    s_xprev[tid] = s_xprior[tid];
                    s_xpost[tid] = xp;
                    out[tid * T_LEN + (t - 1)] = xp;
                }
                __syncthreads();
            }
            if (tid < M_) {
                float acc = 0.f;
#pragma unroll
                for (int k = 0; k < M_; ++k) acc = fmaf(A[tid * M_ + k], s_xpost[k], acc);
                s_xprior[tid] = acc;
            }
            __syncthreads();
            if (wid == 0) {
                for (int j = lane; j < N_; j += 32) {
                    float m = C[j * (M_ + 1) + M_];
#pragma unroll
                    for (int k = 0; k < M_; ++k) m = fmaf(C[j * (M_ + 1) + k], s_xprior[k], m);
                    s_dy[j] = y[j * T_LEN + t] - m;
                }
                __syncwarp();
                float sq = 0.f;
                for (int j = lane; j < N_; j += 32) sq += s_dy[j] * s_dy[j];
#pragma unroll
                for (int o = 16; o; o >>= 1) sq += __shfl_down_sync(0xffffffffu, sq, o);
                sq = __shfl_sync(0xffffffffu, sq, 0);
                float inv = 1.f / fmaxf(sqrtf(sq), 1e-12f);
                for (int j = lane; j < N_; j += 32) g_knet[j] = s_dy[j] * inv;

                float dx = (lane < M_) ? (s_xpost[lane] - s_xprev[lane]) : 0.f;
                float sq2 = dx * dx;
#pragma unroll
                for (int o = 16; o; o >>= 1) sq2 += __shfl_down_sync(0xffffffffu, sq2, o);
                sq2 = __shfl_sync(0xffffffffu, sq2, 0);
                float inv2 = 1.f / fmaxf(sqrtf(sq2), 1e-12f);
                if (lane < M_) g_knet[N_ + lane] = dx * inv2;
                __syncwarp();
                if (lane == 0) {
                    __threadfence();
                    *((volatile unsigned*)&g_knetflag) = (unsigned)(t + 1);
                }
            }
        }

        // ---------- ALL blocks: gi (split rows) into smem ----------
        wait_ctr(&g_l1done, (unsigned)FR_NB * (unsigned)(t + 1));
        {
            const uint4* src = (const uint4*)g_l1h;
            for (int i = tid; i < H1_ / 8; i += NTHR) s_x[i] = src[i];
        }
        __syncthreads();
        {
            int uu = wid & 15, half = wid >> 4;
            int u = bid + NBLK * uu;
            if (u < HID_) {
                const __half* wa = w_ihH + (size_t)u * H1_ + half * 2080;
                const __half* wb = w_ihH + (size_t)(u + HID_) * H1_ + half * 2080;
                const __half* wc = w_ihH + (size_t)(u + 2 * HID_) * H1_ + half * 2080;
                float3 g = dot3_half<260>(wa, wb, wc, s_x + half * 260);
                if (lane == 0) {
                    s_part[wid][0] = g.x;
                    s_part[wid][1] = g.y;
                    s_part[wid][2] = g.z;
                }
            }
        }
        // barrier #1: all gi partials in smem; all g_gh writes globally visible
        grid_barrier2(bid, 2u * (unsigned)t + 1u);

        // ---------- gate (reads g_gh after barrier) ----------
        if (tid < 16) {
            int u = bid + NBLK * tid;
            if (u < HID_) {
                float gir = s_part[tid][0] + s_part[tid + 16][0] + bih[u];
                float giz = s_part[tid][1] + s_part[tid + 16][1] + bih[u + HID_];
                float gin = s_part[tid][2] + s_part[tid + 16][2] + bih[u + 2 * HID_];
                float hold = (t == 0) ? h0[u] : g_hf[u];
                float rg = sigmoidf_(gir + g_gh[u]);
                float zg = sigmoidf_(giz + g_gh[u + HID_]);
                float ng = tanhf(gin + rg * g_gh[u + 2 * HID_]);
                float hv = (1.f - zg) * ng + zg * hold;
                g_hf[u]  = hv;
                g_hh2[u] = __float2half(hv);
            }
        }
        // barrier #2: h(t) published
        grid_barrier2(bid, 2u * (unsigned)t + 2u);
    }

    // ================= epilogue: x_post(T-1) =================
    if (isF) {
        const uint4* src = (const uint4*)g_hh2;
        for (int i = tid; i < HID_ / 8; i += NTHR) s_x[i] = src[i];
        __syncthreads();
        if (wid < L2CH) {
            int r = (bid - 1) * L2CH + wid;
            float v = dot_row<HID_ / 8>(w2H + (size_t)r * HID_, s_x);
            if (lane == 0) s_l2c[wid] = fmaxf(v + b2[r], 0.f);
        }
        __syncthreads();
        if (tid < DOUT) {
            int c0 = (bid - 1) * L2CH;
            float acc = 0.f;
#pragma unroll
            for (int j = 0; j < L2CH; ++j)
                acc = fmaf(w3T[(size_t)(c0 + j) * DOUT + tid], s_l2c[j], acc);
            g_zpart[(bid - 1) * DOUT + tid] = acc;
        }
        signal_done(&g_zdone);
    }
    if (bid == 0) {
        wait_ctr(&g_zdone, (unsigned)FR_NB * (unsigned)T_LEN);
        if (tid < DOUT) {
            float acc = b3[tid];
#pragma unroll
            for (int c = 0; c < FR_NB; ++c) acc += g_zpart[c * DOUT + tid];
            s_z[tid] = acc * 1e-4f;
        }
        __syncthreads();
        if (tid < M_) {
            float acc = 0.f;
#pragma unroll 4
            for (int j = 0; j < N_; ++j) acc = fmaf(s_z[tid * N_ + j], s_dy[j], acc);
            out[tid * T_LEN + (T_LEN - 1)] = s_xprior[tid] + acc;
        }
        __syncthreads();
        // reset sync state for graph replay
        if (tid < NBLK) *((volatile unsigned*)&g_harr[tid]) = 0u;
        if (tid == 0) {
            *((volatile unsigned*)&g_zdone)    = 0u;
            *((volatile unsigned*)&g_knetflag) = 0u;
            *((volatile unsigned*)&g_l1done)   = 0u;
            *((volatile unsigned*)&g_rel)      = 0u;
            __threadfence();
        }
    }
}

// ---------------- launch ----------------
extern "C" void kernel_launch(void* const* d_in, const int* in_sizes, int n_in,
                              void* d_out, int out_size) {
    const float* A    = (const float*)d_in[0];
    const float* C    = (const float*)d_in[1];
    const float* x0   = (const float*)d_in[2];
    const float* h0   = (const float*)d_in[3];
    const float* y    = (const float*)d_in[4];
    const float* W1   = (const float*)d_in[5];
    const float* b1   = (const float*)d_in[6];
    const float* Wih  = (const float*)d_in[7];
    const float* Whh  = (const float*)d_in[8];
    const float* bih  = (const float*)d_in[9];
    const float* bhh  = (const float*)d_in[10];
    const float* W2   = (const float*)d_in[11];
    const float* b2   = (const float*)d_in[12];
    const float* W3   = (const float*)d_in[13];
    const float* b3   = (const float*)d_in[14];
    float* out = (float*)d_out;

    cvt_kernel<<<2048, 256>>>(Wih, Whh, W2, W3);
    kalmannet_kernel<<<NBLK, NTHR>>>(A, C, x0, h0, y, W1, b1, bih, bhh,
                                     b2, b3, out);
}

// round 17
// speedup vs baseline: 1.5758x; 1.1752x over previous
#include <cuda_runtime.h>
#include <cuda_fp16.h>
#include <math.h>

// Problem dims
#define T_LEN 512
#define M_    4
#define N_    48
#define DIN   52
#define H1_   4160
#define HID_  2320
#define G3_   6960
#define H2_   768
#define DOUT  192

#define NBLK  148
#define NTHR  1024
#define NWARP 32

#define OWN_B0  3          // owners: blocks 3..147, 16 contiguous units each
#define FR_NB   48         // front blocks 1..48: W2(16 rows) + z partial + W1
#define W1_PB   87         // W1 rows per front block (48*87 = 4176 >= 4160)

// ---------------- device scratch ----------------
__device__ __align__(16) __half w_ihH[(size_t)G3_ * H1_];
__device__ __align__(16) __half w_hhH[(size_t)G3_ * HID_];
__device__ __align__(16) __half w2H[(size_t)H2_ * HID_];
__device__ __align__(16) float  w3T[(size_t)H2_ * DOUT];   // [l2col][row]

__device__ __align__(16) float  g_hf[HID_];
__device__ __align__(16) __half g_hh2[HID_];
__device__ __align__(16) __half g_l1h[H1_ + 64];
__device__ __align__(16) float  g_zpart[FR_NB * DOUT];
__device__ __align__(16) float  g_knet[DIN + 4];
__device__ unsigned g_zdone, g_l1done, g_knetfl;
__device__ unsigned g_harr[152];
__device__ unsigned g_rel;

// ---------------- conversion kernel ----------------
__device__ __forceinline__ void cvt8(const float* __restrict__ src,
                                     __half* __restrict__ dst, size_t g) {
    const float4* s4 = (const float4*)src;
    float4 a = s4[2 * g], b = s4[2 * g + 1];
    __half2 h0 = __floats2half2_rn(a.x, a.y);
    __half2 h1 = __floats2half2_rn(a.z, a.w);
    __half2 h2 = __floats2half2_rn(b.x, b.y);
    __half2 h3 = __floats2half2_rn(b.z, b.w);
    uint4 o;
    o.x = *(unsigned*)&h0; o.y = *(unsigned*)&h1;
    o.z = *(unsigned*)&h2; o.w = *(unsigned*)&h3;
    ((uint4*)dst)[g] = o;
}

__global__ void cvt_kernel(const float* __restrict__ Wih,
                           const float* __restrict__ Whh,
                           const float* __restrict__ W2,
                           const float* __restrict__ W3) {
    size_t i0 = (size_t)blockIdx.x * blockDim.x + threadIdx.x;
    size_t st = (size_t)gridDim.x * blockDim.x;
    const size_t nIH = (size_t)G3_ * H1_ / 8, nHH = (size_t)G3_ * HID_ / 8;
    const size_t n2 = (size_t)H2_ * HID_ / 8;
    const size_t n3 = (size_t)H2_ * DOUT;
    for (size_t g = i0; g < nIH; g += st) cvt8(Wih, w_ihH, g);
    for (size_t g = i0; g < nHH; g += st) cvt8(Whh, w_hhH, g);
    for (size_t g = i0; g < n2;  g += st) cvt8(W2, w2H, g);
    for (size_t i = i0; i < n3; i += st) {
        size_t c = i / DOUT, r = i % DOUT;
        w3T[i] = W3[r * H2_ + c];
    }
}

// ---------------- sync primitives ----------------
// store-based grid barrier (validated R14-R16)
__device__ __forceinline__ void grid_barrier2(int bid, unsigned tag) {
    __syncthreads();
    if (threadIdx.x == 0) {
        __threadfence();
        *((volatile unsigned*)&g_harr[bid]) = tag;
    }
    if (bid == 0 && threadIdx.x < 32) {
        int lane = threadIdx.x;
        for (;;) {
            unsigned v0 = 0xffffffffu, v1 = 0xffffffffu, v2 = 0xffffffffu;
            unsigned v3 = 0xffffffffu, v4 = 0xffffffffu;
            { int i = lane;       if (i < NBLK) v0 = *((volatile unsigned*)&g_harr[i]); }
            { int i = lane + 32;  if (i < NBLK) v1 = *((volatile unsigned*)&g_harr[i]); }
            { int i = lane + 64;  if (i < NBLK) v2 = *((volatile unsigned*)&g_harr[i]); }
            { int i = lane + 96;  if (i < NBLK) v3 = *((volatile unsigned*)&g_harr[i]); }
            { int i = lane + 128; if (i < NBLK) v4 = *((volatile unsigned*)&g_harr[i]); }
            unsigned mn = min(min(min(v0, v1), min(v2, v3)), v4);
#pragma unroll
            for (int o = 16; o; o >>= 1) {
                unsigned v = __shfl_down_sync(0xffffffffu, mn, o);
                if (v < mn) mn = v;
            }
            mn = __shfl_sync(0xffffffffu, mn, 0);
            if (mn >= tag) break;
        }
        if (lane == 0) { __threadfence(); *((volatile unsigned*)&g_rel) = tag; }
    }
    if (threadIdx.x == 0) {
        while (*((volatile unsigned*)&g_rel) < tag) { }
        __threadfence();
    }
    __syncthreads();
}

__device__ __forceinline__ void wait_ctr(unsigned* ctr, unsigned target) {
    if (threadIdx.x == 0) {
        while (*((volatile unsigned*)ctr) < target) { }
        __threadfence();
    }
    __syncthreads();
}

#define H2AT(u) (*(const __half2*)&(u))

// ---------------- dots (R16 verbatim) ----------------
template <int N8>
__device__ __forceinline__ float3 dot3_half(const __half* __restrict__ wa,
                                            const __half* __restrict__ wb,
                                            const __half* __restrict__ wc,
                                            const uint4* __restrict__ xs) {
    constexpr int KF  = N8 / 32;
    constexpr int REM = N8 % 32;
    const uint4* A  = (const uint4*)wa;
    const uint4* B  = (const uint4*)wb;
    const uint4* Cc = (const uint4*)wc;
    const int lane = threadIdx.x & 31;
    uint4 rA[2], rB[2], rC[2];
#pragma unroll
    for (int s = 0; s < 2; ++s)
        if (s < KF) { int c = s * 32 + lane; rA[s] = A[c]; rB[s] = B[c]; rC[s] = Cc[c]; }
    __half2 z = __float2half2_rn(0.f);
    __half2 a0 = z, a1 = z, b0 = z, b1 = z, c0 = z, c1 = z;
#pragma unroll
    for (int k = 0; k < KF; ++k) {
        const int sl = k & 1;
        uint4 u = rA[sl], v = rB[sl], w = rC[sl];
        if (k + 2 < KF) { int c = (k + 2) * 32 + lane; rA[sl] = A[c]; rB[sl] = B[c]; rC[sl] = Cc[c]; }
        uint4 xv = xs[k * 32 + lane];
        a0 = __hfma2(H2AT(u.x), H2AT(xv.x), a0);
        a1 = __hfma2(H2AT(u.y), H2AT(xv.y), a1);
        a0 = __hfma2(H2AT(u.z), H2AT(xv.z), a0);
        a1 = __hfma2(H2AT(u.w), H2AT(xv.w), a1);
        b0 = __hfma2(H2AT(v.x), H2AT(xv.x), b0);
        b1 = __hfma2(H2AT(v.y), H2AT(xv.y), b1);
        b0 = __hfma2(H2AT(v.z), H2AT(xv.z), b0);
        b1 = __hfma2(H2AT(v.w), H2AT(xv.w), b1);
        c0 = __hfma2(H2AT(w.x), H2AT(xv.x), c0);
        c1 = __hfma2(H2AT(w.y), H2AT(xv.y), c1);
        c0 = __hfma2(H2AT(w.z), H2AT(xv.z), c0);
        c1 = __hfma2(H2AT(w.w), H2AT(xv.w), c1);
    }
    if (REM > 0 && lane < REM) {
        int c = KF * 32 + lane;
        uint4 u = A[c], v = B[c], w = Cc[c], xv = xs[c];
        a0 = __hfma2(H2AT(u.x), H2AT(xv.x), a0);
        a1 = __hfma2(H2AT(u.y), H2AT(xv.y), a1);
        a0 = __hfma2(H2AT(u.z), H2AT(xv.z), a0);
        a1 = __hfma2(H2AT(u.w), H2AT(xv.w), a1);
        b0 = __hfma2(H2AT(v.x), H2AT(xv.x), b0);
        b1 = __hfma2(H2AT(v.y), H2AT(xv.y), b1);
        b0 = __hfma2(H2AT(v.z), H2AT(xv.z), b0);
        b1 = __hfma2(H2AT(v.w), H2AT(xv.w), b1);
        c0 = __hfma2(H2AT(w.x), H2AT(xv.x), c0);
        c1 = __hfma2(H2AT(w.y), H2AT(xv.y), c1);
        c0 = __hfma2(H2AT(w.z), H2AT(xv.z), c0);
        c1 = __hfma2(H2AT(w.w), H2AT(xv.w), c1);
    }
    float2 fa0 = __half22float2(a0), fa1 = __half22float2(a1);
    float2 fb0 = __half22float2(b0), fb1 = __half22float2(b1);
    float2 fc0 = __half22float2(c0), fc1 = __half22float2(c1);
    float ra = (fa0.x + fa0.y) + (fa1.x + fa1.y);
    float rb = (fb0.x + fb0.y) + (fb1.x + fb1.y);
    float rc = (fc0.x + fc0.y) + (fc1.x + fc1.y);
#pragma unroll
    for (int o = 16; o; o >>= 1) {
        ra += __shfl_down_sync(0xffffffffu, ra, o);
        rb += __shfl_down_sync(0xffffffffu, rb, o);
        rc += __shfl_down_sync(0xffffffffu, rc, o);
    }
    return make_float3(ra, rb, rc);
}

template <int N8>
__device__ __forceinline__ float dot_row(const __half* __restrict__ w,
                                         const uint4* __restrict__ xs) {
    constexpr int KF  = N8 / 32;
    constexpr int REM = N8 % 32;
    const uint4* W = (const uint4*)w;
    const int lane = threadIdx.x & 31;
    uint4 rW[4];
#pragma unroll
    for (int s = 0; s < 4; ++s)
        if (s < KF) rW[s] = W[s * 32 + lane];
    __half2 z = __float2half2_rn(0.f);
    __half2 a0 = z, a1 = z, a2 = z, a3 = z;
#pragma unroll
    for (int k = 0; k < KF; ++k) {
        const int sl = k & 3;
        uint4 wv = rW[sl];
        if (k + 4 < KF) rW[sl] = W[(k + 4) * 32 + lane];
        uint4 xv = xs[k * 32 + lane];
        a0 = __hfma2(H2AT(wv.x), H2AT(xv.x), a0);
        a1 = __hfma2(H2AT(wv.y), H2AT(xv.y), a1);
        a2 = __hfma2(H2AT(wv.z), H2AT(xv.z), a2);
        a3 = __hfma2(H2AT(wv.w), H2AT(xv.w), a3);
    }
    if (REM > 0 && lane < REM) {
        int c = KF * 32 + lane;
        uint4 wv = W[c], xv = xs[c];
        a0 = __hfma2(H2AT(wv.x), H2AT(xv.x), a0);
        a1 = __hfma2(H2AT(wv.y), H2AT(xv.y), a1);
        a2 = __hfma2(H2AT(wv.z), H2AT(xv.z), a2);
        a3 = __hfma2(H2AT(wv.w), H2AT(xv.w), a3);
    }
    float2 f0 = __half22float2(a0), f1 = __half22float2(a1);
    float2 f2 = __half22float2(a2), f3 = __half22float2(a3);
    float acc = ((f0.x + f0.y) + (f1.x + f1.y)) + ((f2.x + f2.y) + (f3.x + f3.y));
#pragma unroll
    for (int o = 16; o; o >>= 1) acc += __shfl_down_sync(0xffffffffu, acc, o);
    return acc;
}

__device__ __forceinline__ float sigmoidf_(float x) {
    return 1.f / (1.f + __expf(-x));
}

// ---------------- persistent kernel ----------------
__global__ void __launch_bounds__(NTHR, 1)
kalmannet_kernel(const float* __restrict__ A,   const float* __restrict__ C,
                 const float* __restrict__ x0,  const float* __restrict__ h0,
                 const float* __restrict__ y,   const float* __restrict__ W1,
                 const float* __restrict__ b1,  const float* __restrict__ bih,
                 const float* __restrict__ bhh, const float* __restrict__ b2,
                 const float* __restrict__ b3,  float* __restrict__ out) {
    const int tid  = threadIdx.x;
    const int bid  = blockIdx.x;
    const int wid  = tid >> 5;
    const int lane = tid & 31;

    const bool isOwner = (bid >= OWN_B0);
    const bool isFront = (bid >= 1 && bid <= FR_NB);
    const int  base    = (bid - OWN_B0) * 16;

    __shared__ __align__(16) uint4 s_x[H1_ / 8];       // h(half2) then l1(half2)
    __shared__ __align__(16) float s_gh[32][4];
    __shared__ __align__(16) float s_gi[32][4];
    __shared__ __align__(16) float s_l2c[16];
    __shared__ __align__(16) float s_z[DOUT];
    __shared__ float s_dy[N_];
    __shared__ float s_xprior[M_], s_xpost[M_], s_xprev[M_];

    for (int t = 0; t < T_LEN; ++t) {
        // ---- stage h(t-1) as half2 (blocks 1..147) ----
        if (bid != 0) {
            if (t == 0) {
                for (int i = tid; i < HID_ / 2; i += NTHR) {
                    float2 f = ((const float2*)h0)[i];
                    ((__half2*)s_x)[i] = __floats2half2_rn(f.x, f.y);
                }
            } else {
                const uint4* src = (const uint4*)g_hh2;
                for (int i = tid; i < HID_ / 8; i += NTHR) s_x[i] = src[i];
            }
            __syncthreads();
        }

        // ---- front: W2 row per warp (0..15) + z partial + zdone ----
        if (isFront && t > 0 && wid < 16) {
            int r = (bid - 1) * 16 + wid;
            float v = dot_row<HID_ / 8>(w2H + (size_t)r * HID_, s_x);
            if (lane == 0) s_l2c[wid] = fmaxf(v + b2[r], 0.f);
            asm volatile("bar.sync 1, 512;" ::: "memory");
            if (tid < DOUT) {
                int c0 = (bid - 1) * 16;
                float acc = 0.f;
#pragma unroll
                for (int j = 0; j < 16; ++j)
                    acc = fmaf(w3T[(size_t)(c0 + j) * DOUT + tid], s_l2c[j], acc);
                g_zpart[(bid - 1) * DOUT + tid] = acc;
            }
            asm volatile("bar.sync 1, 512;" ::: "memory");
            if (tid == 0) { __threadfence(); atomicAdd(&g_zdone, 1u); }
        }

        // ---- front: W1 (warps 0..2 compute; warps 0..15 flag) ----
        if (isFront && wid < 16) {
            if (wid < 3) {
                while (*((volatile unsigned*)&g_knetfl) < (unsigned)(t + 1)) { }
                __threadfence();
                if (tid < W1_PB) {
                    int r = (bid - 1) * W1_PB + tid;
                    if (r < H1_) {
                        const float4* w4 = (const float4*)(W1 + (size_t)r * DIN);
                        const float4* k4 = (const float4*)g_knet;
                        float acc = b1[r];
#pragma unroll
                        for (int c = 0; c < DIN / 4; ++c) {
                            float4 a = w4[c], b = k4[c];
                            acc = fmaf(a.x, b.x, acc); acc = fmaf(a.y, b.y, acc);
                            acc = fmaf(a.z, b.z, acc); acc = fmaf(a.w, b.w, acc);
                        }
                        g_l1h[r] = __float2half(fmaxf(acc, 0.f));
                    }
                }
            }
            asm volatile("bar.sync 1, 512;" ::: "memory");
            if (tid == 0) { __threadfence(); atomicAdd(&g_l1done, 1u); }
        }

        // ---- Whh into smem (owners) ----
        if (isOwner) {
            if (isFront) {
                if (wid >= 16) {
#pragma unroll
                    for (int q = 0; q < 2; ++q) {
                        int th = (wid - 16) + q * 16;
                        int u = base + (th >> 1), half = th & 1;
                        float3 g = dot3_half<145>(
                            w_hhH + (size_t)u * HID_ + half * 1160,
                            w_hhH + (size_t)(u + HID_) * HID_ + half * 1160,
                            w_hhH + (size_t)(u + 2 * HID_) * HID_ + half * 1160,
                            s_x + half * 145);
                        if (lane == 0) { s_gh[th][0] = g.x; s_gh[th][1] = g.y; s_gh[th][2] = g.z; }
                    }
                }
            } else {
                int th = wid;
                int u = base + (th >> 1), half = th & 1;
                float3 g = dot3_half<145>(
                    w_hhH + (size_t)u * HID_ + half * 1160,
                    w_hhH + (size_t)(u + HID_) * HID_ + half * 1160,
                    w_hhH + (size_t)(u + 2 * HID_) * HID_ + half * 1160,
                    s_x + half * 145);
                if (lane == 0) { s_gh[th][0] = g.x; s_gh[th][1] = g.y; s_gh[th][2] = g.z; }
            }
        }

        // ---- block 0: serial chain -> knet ----
        if (bid == 0) {
            if (t > 0) {
                wait_ctr(&g_zdone, (unsigned)FR_NB * (unsigned)t);
                if (tid < DOUT) {
                    float acc = b3[tid];
#pragma unroll 8
                    for (int c = 0; c < FR_NB; ++c) acc += g_zpart[c * DOUT + tid];
                    s_z[tid] = acc * 1e-4f;
                }
                __syncthreads();
            }
            if (wid == 0) {
                if (t == 0) {
                    if (lane < M_) { s_xpost[lane] = x0[lane]; s_xprev[lane] = x0[lane]; }
                    __syncwarp();
                } else {
                    if (lane < M_) {
                        float acc = 0.f;
#pragma unroll 4
                        for (int j = 0; j < N_; ++j)
                            acc = fmaf(s_z[lane * N_ + j], s_dy[j], acc);
                        float xp = s_xprior[lane] + acc;
                        s_xprev[lane] = s_xprior[lane];
                        s_xpost[lane] = xp;
                        out[lane * T_LEN + (t - 1)] = xp;
                    }
                    __syncwarp();
                }
                if (lane < M_) {
                    float acc = 0.f;
#pragma unroll
                    for (int k = 0; k < M_; ++k) acc = fmaf(A[lane * M_ + k], s_xpost[k], acc);
                    s_xprior[lane] = acc;
                }
                __syncwarp();
                for (int j = lane; j < N_; j += 32) {
                    float m = C[j * (M_ + 1) + M_];
#pragma unroll
                    for (int k = 0; k < M_; ++k) m = fmaf(C[j * (M_ + 1) + k], s_xprior[k], m);
                    s_dy[j] = y[j * T_LEN + t] - m;
                }
                __syncwarp();
                float sq = 0.f;
                for (int j = lane; j < N_; j += 32) sq += s_dy[j] * s_dy[j];
#pragma unroll
                for (int o = 16; o; o >>= 1) sq += __shfl_down_sync(0xffffffffu, sq, o);
                sq = __shfl_sync(0xffffffffu, sq, 0);
                float inv = 1.f / fmaxf(sqrtf(sq), 1e-12f);
                for (int j = lane; j < N_; j += 32) g_knet[j] = s_dy[j] * inv;

                float dx = (lane < M_) ? (s_xpost[lane] - s_xprev[lane]) : 0.f;
                float sq2 = dx * dx;
#pragma unroll
                for (int o = 16; o; o >>= 1) sq2 += __shfl_down_sync(0xffffffffu, sq2, o);
                sq2 = __shfl_sync(0xffffffffu, sq2, 0);
                float inv2 = 1.f / fmaxf(sqrtf(sq2), 1e-12f);
                if (lane < M_) g_knet[N_ + lane] = dx * inv2;
                __syncwarp();
                if (lane == 0) {
                    __threadfence();
                    *((volatile unsigned*)&g_knetfl) = (unsigned)(t + 1);
                }
            }
        }

        // ---- owners: wait l1, stage, gi, gate ----
        if (isOwner) {
            wait_ctr(&g_l1done, (unsigned)FR_NB * (unsigned)(t + 1));
            {
                const uint4* src = (const uint4*)g_l1h;
                for (int i = tid; i < H1_ / 8; i += NTHR) s_x[i] = src[i];
            }
            __syncthreads();
            {
                int th = wid;
                int u = base + (th >> 1), half = th & 1;
                float3 g = dot3_half<260>(
                    w_ihH + (size_t)u * H1_ + half * 2080,
                    w_ihH + (size_t)(u + HID_) * H1_ + half * 2080,
                    w_ihH + (size_t)(u + 2 * HID_) * H1_ + half * 2080,
                    s_x + half * 260);
                if (lane == 0) { s_gi[th][0] = g.x; s_gi[th][1] = g.y; s_gi[th][2] = g.z; }
            }
            __syncthreads();
            if (tid < 16) {
                int u = base + tid;
                float gir = s_gi[2 * tid][0] + s_gi[2 * tid + 1][0] + bih[u];
                float giz = s_gi[2 * tid][1] + s_gi[2 * tid + 1][1] + bih[u + HID_];
                float gin = s_gi[2 * tid][2] + s_gi[2 * tid + 1][2] + bih[u + 2 * HID_];
                float ghr = s_gh[2 * tid][0] + s_gh[2 * tid + 1][0] + bhh[u];
                float ghz = s_gh[2 * tid][1] + s_gh[2 * tid + 1][1] + bhh[u + HID_];
                float ghn = s_gh[2 * tid][2] + s_gh[2 * tid + 1][2] + bhh[u + 2 * HID_];
                float hold = (t == 0) ? h0[u] : g_hf[u];
                float rg = sigmoidf_(gir + ghr);
                float zg = sigmoidf_(giz + ghz);
                float ng = tanhf(gin + rg * ghn);
                float hv = (1.f - zg) * ng + zg * hold;
                g_hf[u]  = hv;
                g_hh2[u] = __float2half(hv);
            }
        }

        grid_barrier2(bid, (unsigned)(t + 1));
    }

    // ================= epilogue: x_post(T-1) =================
    if (isFront) {
        const uint4* src = (const uint4*)g_hh2;
        for (int i = tid; i < HID_ / 8; i += NTHR) s_x[i] = src[i];
        __syncthreads();
        if (wid < 16) {
            int r = (bid - 1) * 16 + wid;
            float v = dot_row<HID_ / 8>(w2H + (size_t)r * HID_, s_x);
            if (lane == 0) s_l2c[wid] = fmaxf(v + b2[r], 0.f);
            asm volatile("bar.sync 1, 512;" ::: "memory");
            if (tid < DOUT) {
                int c0 = (bid - 1) * 16;
                float acc = 0.f;
#pragma unroll
                for (int j = 0; j < 16; ++j)
                    acc = fmaf(w3T[(size_t)(c0 + j) * DOUT + tid], s_l2c[j], acc);
                g_zpart[(bid - 1) * DOUT + tid] = acc;
            }
            asm volatile("bar.sync 1, 512;" ::: "memory");
            if (tid == 0) { __threadfence(); atomicAdd(&g_zdone, 1u); }
        }
    }
    if (bid == 0) {
        wait_ctr(&g_zdone, (unsigned)FR_NB * (unsigned)T_LEN);
        if (tid < DOUT) {
            float acc = b3[tid];
#pragma unroll 8
            for (int c = 0; c < FR_NB; ++c) acc += g_zpart[c * DOUT + tid];
            s_z[tid] = acc * 1e-4f;
        }
        __syncthreads();
        if (tid < M_) {
            float acc = 0.f;
#pragma unroll 4
            for (int j = 0; j < N_; ++j) acc = fmaf(s_z[tid * N_ + j], s_dy[j], acc);
            out[tid * T_LEN + (T_LEN - 1)] = s_xprior[tid] + acc;
        }
        __syncthreads();
        // reset sync state for graph replay
        if (tid < NBLK) *((volatile unsigned*)&g_harr[tid]) = 0u;
        if (tid == 0) {
            *((volatile unsigned*)&g_zdone)  = 0u;
            *((volatile unsigned*)&g_l1done) = 0u;
            *((volatile unsigned*)&g_knetfl) = 0u;
            *((volatile unsigned*)&g_rel)    = 0u;
            __threadfence();
        }
    }
}

// ---------------- launch ----------------
extern "C" void kernel_launch(void* const* d_in, const int* in_sizes, int n_in,
                              void* d_out, int out_size) {
    const float* A    = (const float*)d_in[0];
    const float* C    = (const float*)d_in[1];
    const float* x0   = (const float*)d_in[2];
    const float* h0   = (const float*)d_in[3];
    const float* y    = (const float*)d_in[4];
    const float* W1   = (const float*)d_in[5];
    const float* b1   = (const float*)d_in[6];
    const float* Wih  = (const float*)d_in[7];
    const float* Whh  = (const float*)d_in[8];
    const float* bih  = (const float*)d_in[9];
    const float* bhh  = (const float*)d_in[10];
    const float* W2   = (const float*)d_in[11];
    const float* b2   = (const float*)d_in[12];
    const float* W3   = (const float*)d_in[13];
    const float* b3   = (const float*)d_in[14];
    float* out = (float*)d_out;

    cvt_kernel<<<2048, 256>>>(Wih, Whh, W2, W3);
    kalmannet_kernel<<<NBLK, NTHR>>>(A, C, x0, h0, y, W1, b1, bih, bhh,
                                     b2, b3, out);
}